// round 9
// baseline (speedup 1.0000x reference)
#include <cuda_runtime.h>
#include <cuda_bf16.h>
#include <cstdint>

#define N_NODES 50000
#define N_EDGES 800000

#define M_TILE   128
#define THREADS  512
#define N_BLOCKS ((N_NODES + M_TILE - 1) / M_TILE)   // 391

// ---------------------------------------------------------------------------
// Device scratch. g_flag invariant: zero before every kernel_launch invocation
// (zero at module load; fused kernel re-zeroes its rows after use each run).
// g_Wfrag: B fragments for mma.m16n8k16, packed {bh0,bh1,bl0,bl1} per
// (kt, nt, lane). Identical for all CTAs -> L1-resident reads.
// ---------------------------------------------------------------------------
__device__ int g_flag[N_NODES];
__device__ __align__(16) uint4 g_Wfrag[8 * 16 * 32];      // 64 KB

// ---------------------------------------------------------------------------
// Blocked SW128 atom layout for a [128 x 128] bf16 tile (A side only now).
// atom = 8 rows x 64 bf16 (1024B); atom index = (r>>3) + (k>>6)*16.
// ---------------------------------------------------------------------------
__host__ __device__ __forceinline__ uint32_t tile_off(int r, int k) {
    uint32_t off = ((uint32_t)((r >> 3) + ((k >> 6) << 4))) * 1024u
                 + (uint32_t)(r & 7) * 128u + (uint32_t)(k & 63) * 2u;
    return off ^ ((off >> 3) & 0x70);
}

// ---------------------------------------------------------------------------
__device__ __forceinline__ uint32_t smem_u32(const void* p) {
    uint32_t a;
    asm("{ .reg .u64 t; cvta.to.shared.u64 t, %1; cvt.u32.u64 %0, t; }" : "=r"(a) : "l"(p));
    return a;
}

__device__ __forceinline__ void mma16816(float* d, const uint32_t* a, uint32_t b0, uint32_t b1) {
    asm volatile(
        "mma.sync.aligned.m16n8k16.row.col.f32.bf16.bf16.f32 "
        "{%0,%1,%2,%3}, {%4,%5,%6,%7}, {%8,%9}, {%0,%1,%2,%3};"
        : "+f"(d[0]), "+f"(d[1]), "+f"(d[2]), "+f"(d[3])
        : "r"(a[0]), "r"(a[1]), "r"(a[2]), "r"(a[3]), "r"(b0), "r"(b1));
}

__device__ __forceinline__ void ldmx4(uint32_t* r, uint32_t addr) {
    asm volatile("ldmatrix.sync.aligned.m8n8.x4.shared.b16 {%0,%1,%2,%3}, [%4];"
                 : "=r"(r[0]), "=r"(r[1]), "=r"(r[2]), "=r"(r[3]) : "r"(addr));
}

// ---------------------------------------------------------------------------
// Kernel 1: W fragment build (blocks 0..15) + edge-dst marking (blocks 16..)
// Fragment for (kt, nt, lane): n = 8*nt + lane/4, k0 = 16*kt + 2*(lane%4);
//   bh0 = hi{Wt[n][k0], Wt[n][k0+1]},  bh1 = same at k0+8;  bl* = lo parts.
// Wt[n][k] = Wv[k*128 + n].
// ---------------------------------------------------------------------------
#define WF_BLOCKS   16
#define MARK_CHUNK  (N_EDGES / 4)
#define MARK_BLOCKS ((MARK_CHUNK + 255) / 256)

__global__ void prep_mark_kernel(const float* __restrict__ Wv,
                                 const int* __restrict__ edge_index) {
    int b = blockIdx.x;
    if (b < WF_BLOCKS) {
        int idx = b * 256 + threadIdx.x;          // 0..4095 = (kt*16+nt)*32+lane
        int lane = idx & 31;
        int nt   = (idx >> 5) & 15;
        int kt   = idx >> 9;
        int n  = 8 * nt + (lane >> 2);
        int k0 = 16 * kt + 2 * (lane & 3);

        float w00 = Wv[(size_t)k0 * 128 + n];
        float w01 = Wv[(size_t)(k0 + 1) * 128 + n];
        float w10 = Wv[(size_t)(k0 + 8) * 128 + n];
        float w11 = Wv[(size_t)(k0 + 9) * 128 + n];

        __nv_bfloat162 h0, h1, l0, l1;
        h0.x = __float2bfloat16(w00); h0.y = __float2bfloat16(w01);
        h1.x = __float2bfloat16(w10); h1.y = __float2bfloat16(w11);
        l0.x = __float2bfloat16(w00 - __bfloat162float(h0.x));
        l0.y = __float2bfloat16(w01 - __bfloat162float(h0.y));
        l1.x = __float2bfloat16(w10 - __bfloat162float(h1.x));
        l1.y = __float2bfloat16(w11 - __bfloat162float(h1.y));

        g_Wfrag[idx] = make_uint4(*(uint32_t*)&h0, *(uint32_t*)&h1,
                                  *(uint32_t*)&l0, *(uint32_t*)&l1);
    } else {
        int idx = (b - WF_BLOCKS) * 256 + threadIdx.x;
        if (idx < MARK_CHUNK) {
            int4 d = ((const int4*)(edge_index + N_EDGES))[idx];
            if ((unsigned)d.x < N_NODES) g_flag[d.x] = 1;
            if ((unsigned)d.y < N_NODES) g_flag[d.y] = 1;
            if ((unsigned)d.z < N_NODES) g_flag[d.z] = 1;
            if ((unsigned)d.w < N_NODES) g_flag[d.w] = 1;
        }
    }
}

// ---------------------------------------------------------------------------
// Fused: V = x@Wv (bf16-split mma.sync, B from global fragments)
//        -> h = x + V*flag -> LayerNorm.
// CTA = 128 rows, 512 threads = 16 warps; warp w: rows 16*(w>>1)..+15,
// column half 64*(w&1)..+63. 2 CTAs/SM via launch_bounds.
// ---------------------------------------------------------------------------
#define SM_GAMMA  0
#define SM_BETA   512
#define SM_PSUM   1024
#define SM_PSQ    2048
#define SM_XHI    3072
#define SM_XLO    (SM_XHI + 32768)
#define SM_TOTAL  (SM_XLO + 32768)     // 67 KB

__global__ __launch_bounds__(THREADS, 2) void fused_v_ln_kernel(
    const float* __restrict__ x,
    const float* __restrict__ gamma,
    const float* __restrict__ beta,
    float* __restrict__ out)
{
    extern __shared__ char smem[];
    const uint32_t sbase = smem_u32(smem);
    const int tid  = threadIdx.x;
    const int w    = tid >> 5;
    const int lane = tid & 31;
    const int rw   = w >> 1;           // row group 0..7
    const int ch   = w & 1;            // column half
    const int row0 = blockIdx.x * M_TILE;

    if (tid < 128) {
        ((float*)(smem + SM_GAMMA))[tid] = gamma[tid];
        ((float*)(smem + SM_BETA))[tid]  = beta[tid];
    }

    // Load x tile (coalesced float4), split to bf16 hi/lo, store swizzled
#pragma unroll
    for (int i = 0; i < 8; i++) {
        int idx4 = tid + i * 512;            // 0..4095
        int r  = idx4 >> 5;
        int c4 = idx4 & 31;
        int rr = min(row0 + r, N_NODES - 1);
        float4 v = ((const float4*)x)[(size_t)rr * 32 + c4];

        __nv_bfloat162 h01, h23, l01, l23;
        h01.x = __float2bfloat16(v.x); h01.y = __float2bfloat16(v.y);
        h23.x = __float2bfloat16(v.z); h23.y = __float2bfloat16(v.w);
        l01.x = __float2bfloat16(v.x - __bfloat162float(h01.x));
        l01.y = __float2bfloat16(v.y - __bfloat162float(h01.y));
        l23.x = __float2bfloat16(v.z - __bfloat162float(h23.x));
        l23.y = __float2bfloat16(v.w - __bfloat162float(h23.y));

        uint32_t off = tile_off(r, c4 << 2);
        *(uint2*)(smem + SM_XHI + off) = make_uint2(*(uint32_t*)&h01, *(uint32_t*)&h23);
        *(uint2*)(smem + SM_XLO + off) = make_uint2(*(uint32_t*)&l01, *(uint32_t*)&l23);
    }
    __syncthreads();

    // ---- A-side ldmatrix address precompute -------------------------------
    const int selA = lane >> 3;
    const int rA   = 16 * rw + (lane & 7) + ((selA & 1) << 3);
    const int kOffA = (selA & 2) << 2;                       // 0 or 8
    const uint32_t rbaseA = (uint32_t)(rA >> 3) * 1024u + (uint32_t)(rA & 7) * 128u;
    const uint32_t xorA   = (uint32_t)(rA & 7) << 4;

    // B fragment pointer: g_Wfrag[(kt*16 + 8*ch + nt)*32 + lane]
    const uint4* fragp = g_Wfrag + (8 * ch) * 32 + lane;

    float acc[8][4];
#pragma unroll
    for (int nt = 0; nt < 8; nt++)
#pragma unroll
        for (int i = 0; i < 4; i++) acc[nt][i] = 0.0f;

#pragma unroll
    for (int kt = 0; kt < 8; kt++) {
        const uint32_t katomA = (uint32_t)(((16 * kt + kOffA) >> 6) << 14);
        const uint32_t klowA  = (uint32_t)(((16 * kt + kOffA) & 63) * 2);
        const uint32_t offA   = rbaseA + katomA + (klowA ^ xorA);

        uint32_t ah[4], al[4];
        ldmx4(ah, sbase + SM_XHI + offA);
        ldmx4(al, sbase + SM_XLO + offA);

        const uint4* fk = fragp + kt * 512;
#pragma unroll
        for (int nt = 0; nt < 8; nt++) {
            uint4 f = __ldg(fk + nt * 32);     // {bh0, bh1, bl0, bl1}
            mma16816(acc[nt], ah, f.x, f.y);
            mma16816(acc[nt], ah, f.z, f.w);
            mma16816(acc[nt], al, f.x, f.y);
        }
    }

    // ---- epilogue ---------------------------------------------------------
    // Thread owns rows r0 = 16*rw + lane/4, r1 = r0+8; cols 64*ch + 8*nt + 2*(lane&3).
    const int g  = lane >> 2;
    const int t  = lane & 3;
    const int r0 = 16 * rw + g;
    const int r1 = r0 + 8;
    const int row0g = row0 + r0;
    const int row1g = row0 + r1;
    const int rc0 = min(row0g, N_NODES - 1);
    const int rc1 = min(row1g, N_NODES - 1);

    const float fac0 = (float)g_flag[rc0];
    const float fac1 = (float)g_flag[rc1];

    float s0 = 0.0f, s1 = 0.0f;
#pragma unroll
    for (int nt = 0; nt < 8; nt++) {
        const int c = 64 * ch + 8 * nt + 2 * t;
        float2 x0 = *(const float2*)(x + (size_t)rc0 * 128 + c);
        float2 x1 = *(const float2*)(x + (size_t)rc1 * 128 + c);
        float h00 = fmaf(acc[nt][0], fac0, x0.x);
        float h01 = fmaf(acc[nt][1], fac0, x0.y);
        float h10 = fmaf(acc[nt][2], fac1, x1.x);
        float h11 = fmaf(acc[nt][3], fac1, x1.y);
        acc[nt][0] = h00; acc[nt][1] = h01;
        acc[nt][2] = h10; acc[nt][3] = h11;
        s0 += h00 + h01;
        s1 += h10 + h11;
    }
    s0 += __shfl_xor_sync(0xffffffffu, s0, 1);
    s0 += __shfl_xor_sync(0xffffffffu, s0, 2);
    s1 += __shfl_xor_sync(0xffffffffu, s1, 1);
    s1 += __shfl_xor_sync(0xffffffffu, s1, 2);

    float* psum = (float*)(smem + SM_PSUM);
    if (t == 0) { psum[r0 * 2 + ch] = s0; psum[r1 * 2 + ch] = s1; }
    __syncthreads();

    // re-zero flags for next replay (all facs already read)
    if (tid < 128) {
        int rz = row0 + tid;
        if (rz < N_NODES) g_flag[rz] = 0;
    }

    const float mu0 = (psum[r0 * 2] + psum[r0 * 2 + 1]) * (1.0f / 128.0f);
    const float mu1 = (psum[r1 * 2] + psum[r1 * 2 + 1]) * (1.0f / 128.0f);

    float q0 = 0.0f, q1 = 0.0f;
#pragma unroll
    for (int nt = 0; nt < 8; nt++) {
        float d00 = acc[nt][0] - mu0, d01 = acc[nt][1] - mu0;
        float d10 = acc[nt][2] - mu1, d11 = acc[nt][3] - mu1;
        q0 = fmaf(d00, d00, fmaf(d01, d01, q0));
        q1 = fmaf(d10, d10, fmaf(d11, d11, q1));
    }
    q0 += __shfl_xor_sync(0xffffffffu, q0, 1);
    q0 += __shfl_xor_sync(0xffffffffu, q0, 2);
    q1 += __shfl_xor_sync(0xffffffffu, q1, 1);
    q1 += __shfl_xor_sync(0xffffffffu, q1, 2);

    float* psq = (float*)(smem + SM_PSQ);
    if (t == 0) { psq[r0 * 2 + ch] = q0; psq[r1 * 2 + ch] = q1; }
    __syncthreads();

    const float inv0 = rsqrtf((psq[r0 * 2] + psq[r0 * 2 + 1]) * (1.0f / 128.0f) + 1e-5f);
    const float inv1 = rsqrtf((psq[r1 * 2] + psq[r1 * 2 + 1]) * (1.0f / 128.0f) + 1e-5f);

    const float* sg = (const float*)(smem + SM_GAMMA);
    const float* sb = (const float*)(smem + SM_BETA);
#pragma unroll
    for (int nt = 0; nt < 8; nt++) {
        const int c = 64 * ch + 8 * nt + 2 * t;
        float2 gm = *(const float2*)(sg + c);
        float2 bt = *(const float2*)(sb + c);
        if (row0g < N_NODES) {
            float2 o;
            o.x = fmaf((acc[nt][0] - mu0) * inv0, gm.x, bt.x);
            o.y = fmaf((acc[nt][1] - mu0) * inv0, gm.y, bt.y);
            *(float2*)(out + (size_t)row0g * 128 + c) = o;
        }
        if (row1g < N_NODES) {
            float2 o;
            o.x = fmaf((acc[nt][2] - mu1) * inv1, gm.x, bt.x);
            o.y = fmaf((acc[nt][3] - mu1) * inv1, gm.y, bt.y);
            *(float2*)(out + (size_t)row1g * 128 + c) = o;
        }
    }
}

// ---------------------------------------------------------------------------
extern "C" void kernel_launch(void* const* d_in, const int* in_sizes, int n_in,
                              void* d_out, int out_size)
{
    const float* x          = (const float*)d_in[0];
    const int*   edge_index = (const int*)d_in[1];
    const float* Wv         = (const float*)d_in[5];
    const float* gamma      = (const float*)d_in[7];
    const float* beta       = (const float*)d_in[8];
    float*       out        = (float*)d_out;

    cudaFuncSetAttribute(fused_v_ln_kernel,
                         cudaFuncAttributeMaxDynamicSharedMemorySize, SM_TOTAL);

    prep_mark_kernel<<<WF_BLOCKS + MARK_BLOCKS, 256>>>(Wv, edge_index);
    fused_v_ln_kernel<<<N_BLOCKS, THREADS, SM_TOTAL>>>(x, gamma, beta, out);
}

// round 10
// speedup vs baseline: 1.0021x; 1.0021x over previous
#include <cuda_runtime.h>
#include <cuda_bf16.h>
#include <cstdint>

#define N_NODES 50000
#define N_EDGES 800000

#define M_TILE   64
#define THREADS  256
#define N_BLOCKS ((N_NODES + M_TILE - 1) / M_TILE)   // 782

// ---------------------------------------------------------------------------
// Device scratch. g_flag invariant: zero before every kernel_launch invocation
// (zero at module load; fused kernel re-zeroes its rows after use each run).
// g_Wfrag: B fragments for mma.m16n8k16, packed {bh0,bh1,bl0,bl1} per
// (kt, nt, lane). Identical for all CTAs -> L1-resident reads.
// ---------------------------------------------------------------------------
__device__ int g_flag[N_NODES];
__device__ __align__(16) uint4 g_Wfrag[8 * 16 * 32];      // 64 KB

// ---------------------------------------------------------------------------
__device__ __forceinline__ void mma16816(float* d, const uint32_t* a, uint32_t b0, uint32_t b1) {
    asm volatile(
        "mma.sync.aligned.m16n8k16.row.col.f32.bf16.bf16.f32 "
        "{%0,%1,%2,%3}, {%4,%5,%6,%7}, {%8,%9}, {%0,%1,%2,%3};"
        : "+f"(d[0]), "+f"(d[1]), "+f"(d[2]), "+f"(d[3])
        : "r"(a[0]), "r"(a[1]), "r"(a[2]), "r"(a[3]), "r"(b0), "r"(b1));
}

// Split a float2 into packed bf16x2 hi and lo (v = hi + lo to ~2^-18 rel)
__device__ __forceinline__ void split2(float2 v, uint32_t& hi, uint32_t& lo) {
    __nv_bfloat162 h, l;
    h.x = __float2bfloat16(v.x);
    h.y = __float2bfloat16(v.y);
    l.x = __float2bfloat16(v.x - __bfloat162float(h.x));
    l.y = __float2bfloat16(v.y - __bfloat162float(h.y));
    hi = *(uint32_t*)&h;
    lo = *(uint32_t*)&l;
}

// ---------------------------------------------------------------------------
// Kernel 1: W fragment build (blocks 0..15) + edge-dst marking (blocks 16..)
// Fragment for (kt, nt, lane): n = 8*nt + lane/4, k0 = 16*kt + 2*(lane%4);
//   bh0 = hi{Wt[n][k0], Wt[n][k0+1]},  bh1 = same at k0+8;  bl* = lo parts.
// Wt[n][k] = Wv[k*128 + n].
// ---------------------------------------------------------------------------
#define WF_BLOCKS   16
#define MARK_CHUNK  (N_EDGES / 4)
#define MARK_BLOCKS ((MARK_CHUNK + 255) / 256)

__global__ void prep_mark_kernel(const float* __restrict__ Wv,
                                 const int* __restrict__ edge_index) {
    int b = blockIdx.x;
    if (b < WF_BLOCKS) {
        int idx = b * 256 + threadIdx.x;          // (kt*16+nt)*32+lane
        int lane = idx & 31;
        int nt   = (idx >> 5) & 15;
        int kt   = idx >> 9;
        int n  = 8 * nt + (lane >> 2);
        int k0 = 16 * kt + 2 * (lane & 3);

        float w00 = Wv[(size_t)k0 * 128 + n];
        float w01 = Wv[(size_t)(k0 + 1) * 128 + n];
        float w10 = Wv[(size_t)(k0 + 8) * 128 + n];
        float w11 = Wv[(size_t)(k0 + 9) * 128 + n];

        uint32_t h0, l0, h1, l1;
        split2(make_float2(w00, w01), h0, l0);
        split2(make_float2(w10, w11), h1, l1);
        g_Wfrag[idx] = make_uint4(h0, h1, l0, l1);
    } else {
        int idx = (b - WF_BLOCKS) * 256 + threadIdx.x;
        if (idx < MARK_CHUNK) {
            int4 d = ((const int4*)(edge_index + N_EDGES))[idx];
            if ((unsigned)d.x < N_NODES) g_flag[d.x] = 1;
            if ((unsigned)d.y < N_NODES) g_flag[d.y] = 1;
            if ((unsigned)d.z < N_NODES) g_flag[d.z] = 1;
            if ((unsigned)d.w < N_NODES) g_flag[d.w] = 1;
        }
    }
}

// ---------------------------------------------------------------------------
// Fused: V = x@Wv (bf16-split mma.sync; A direct from gmem, B from global
// fragments) -> h = x + V*flag -> LayerNorm.
// CTA = 64 rows, 256 threads = 8 warps; warp w: rows 16*(w>>1)..+15,
// column half 64*(w&1)..+63. No smem staging; warps run unsynchronized
// until the tiny LayerNorm half-combine.
// ---------------------------------------------------------------------------
__global__ __launch_bounds__(THREADS) void fused_v_ln_kernel(
    const float* __restrict__ x,
    const float* __restrict__ gamma,
    const float* __restrict__ beta,
    float* __restrict__ out)
{
    __shared__ float sg[128], sb[128];
    __shared__ float psum[M_TILE * 2], psq[M_TILE * 2];

    const int tid  = threadIdx.x;
    const int w    = tid >> 5;
    const int lane = tid & 31;
    const int rw   = w >> 1;           // row group 0..3
    const int ch   = w & 1;            // column half
    const int row0 = blockIdx.x * M_TILE;

    if (tid < 128) { sg[tid] = gamma[tid]; sb[tid] = beta[tid]; }

    const int g = lane >> 2;           // 0..7
    const int t = lane & 3;

    // Thread's two rows (A fragment rows g, g+8 of this warp's 16-row group)
    const int r0 = 16 * rw + g;        // 0..63 within tile
    const int r1 = r0 + 8;
    const int row0g = row0 + r0;
    const int row1g = row0 + r1;
    const int rc0 = min(row0g, N_NODES - 1);
    const int rc1 = min(row1g, N_NODES - 1);

    const float2* xr0 = (const float2*)(x + (size_t)rc0 * 128);
    const float2* xr1 = (const float2*)(x + (size_t)rc1 * 128);

    // B fragment pointer: g_Wfrag[(kt*16 + 8*ch + nt)*32 + lane]
    const uint4* fragp = g_Wfrag + (8 * ch) * 32 + lane;

    float acc[8][4];
#pragma unroll
    for (int nt = 0; nt < 8; nt++)
#pragma unroll
        for (int i = 0; i < 4; i++) acc[nt][i] = 0.0f;

#pragma unroll
    for (int kt = 0; kt < 8; kt++) {
        // A fragments straight from gmem: cols 16kt+2t(+1) and +8(+9)
        const int c2 = 8 * kt + t;                 // float2 index
        float2 v00 = __ldg(xr0 + c2);
        float2 v01 = __ldg(xr0 + c2 + 4);
        float2 v10 = __ldg(xr1 + c2);
        float2 v11 = __ldg(xr1 + c2 + 4);

        uint32_t ah[4], al[4];
        split2(v00, ah[0], al[0]);
        split2(v10, ah[1], al[1]);
        split2(v01, ah[2], al[2]);
        split2(v11, ah[3], al[3]);

        const uint4* fk = fragp + kt * 512;
#pragma unroll
        for (int nt = 0; nt < 8; nt++) {
            uint4 f = __ldg(fk + nt * 32);         // {bh0, bh1, bl0, bl1}
            mma16816(acc[nt], ah, f.x, f.y);       // hi*hi
            mma16816(acc[nt], ah, f.z, f.w);       // hi*lo
            mma16816(acc[nt], al, f.x, f.y);       // lo*hi
        }
    }

    // ---- epilogue ---------------------------------------------------------
    const float fac0 = (float)g_flag[rc0];
    const float fac1 = (float)g_flag[rc1];

    float s0 = 0.0f, s1 = 0.0f;
#pragma unroll
    for (int nt = 0; nt < 8; nt++) {
        const int c = 64 * ch + 8 * nt + 2 * t;
        float2 x0 = *(const float2*)(x + (size_t)rc0 * 128 + c);
        float2 x1 = *(const float2*)(x + (size_t)rc1 * 128 + c);
        float h00 = fmaf(acc[nt][0], fac0, x0.x);
        float h01 = fmaf(acc[nt][1], fac0, x0.y);
        float h10 = fmaf(acc[nt][2], fac1, x1.x);
        float h11 = fmaf(acc[nt][3], fac1, x1.y);
        acc[nt][0] = h00; acc[nt][1] = h01;
        acc[nt][2] = h10; acc[nt][3] = h11;
        s0 += h00 + h01;
        s1 += h10 + h11;
    }
    s0 += __shfl_xor_sync(0xffffffffu, s0, 1);
    s0 += __shfl_xor_sync(0xffffffffu, s0, 2);
    s1 += __shfl_xor_sync(0xffffffffu, s1, 1);
    s1 += __shfl_xor_sync(0xffffffffu, s1, 2);

    if (t == 0) { psum[r0 * 2 + ch] = s0; psum[r1 * 2 + ch] = s1; }
    __syncthreads();

    // re-zero flags for next graph replay (all facs of this CTA already read)
    if (tid < M_TILE) {
        int rz = row0 + tid;
        if (rz < N_NODES) g_flag[rz] = 0;
    }

    const float mu0 = (psum[r0 * 2] + psum[r0 * 2 + 1]) * (1.0f / 128.0f);
    const float mu1 = (psum[r1 * 2] + psum[r1 * 2 + 1]) * (1.0f / 128.0f);

    float q0 = 0.0f, q1 = 0.0f;
#pragma unroll
    for (int nt = 0; nt < 8; nt++) {
        float d00 = acc[nt][0] - mu0, d01 = acc[nt][1] - mu0;
        float d10 = acc[nt][2] - mu1, d11 = acc[nt][3] - mu1;
        q0 = fmaf(d00, d00, fmaf(d01, d01, q0));
        q1 = fmaf(d10, d10, fmaf(d11, d11, q1));
    }
    q0 += __shfl_xor_sync(0xffffffffu, q0, 1);
    q0 += __shfl_xor_sync(0xffffffffu, q0, 2);
    q1 += __shfl_xor_sync(0xffffffffu, q1, 1);
    q1 += __shfl_xor_sync(0xffffffffu, q1, 2);

    if (t == 0) { psq[r0 * 2 + ch] = q0; psq[r1 * 2 + ch] = q1; }
    __syncthreads();

    const float inv0 = rsqrtf((psq[r0 * 2] + psq[r0 * 2 + 1]) * (1.0f / 128.0f) + 1e-5f);
    const float inv1 = rsqrtf((psq[r1 * 2] + psq[r1 * 2 + 1]) * (1.0f / 128.0f) + 1e-5f);

#pragma unroll
    for (int nt = 0; nt < 8; nt++) {
        const int c = 64 * ch + 8 * nt + 2 * t;
        float2 gm = *(const float2*)(sg + c);
        float2 bt = *(const float2*)(sb + c);
        if (row0g < N_NODES) {
            float2 o;
            o.x = fmaf((acc[nt][0] - mu0) * inv0, gm.x, bt.x);
            o.y = fmaf((acc[nt][1] - mu0) * inv0, gm.y, bt.y);
            *(float2*)(out + (size_t)row0g * 128 + c) = o;
        }
        if (row1g < N_NODES) {
            float2 o;
            o.x = fmaf((acc[nt][2] - mu1) * inv1, gm.x, bt.x);
            o.y = fmaf((acc[nt][3] - mu1) * inv1, gm.y, bt.y);
            *(float2*)(out + (size_t)row1g * 128 + c) = o;
        }
    }
}

// ---------------------------------------------------------------------------
extern "C" void kernel_launch(void* const* d_in, const int* in_sizes, int n_in,
                              void* d_out, int out_size)
{
    const float* x          = (const float*)d_in[0];
    const int*   edge_index = (const int*)d_in[1];
    const float* Wv         = (const float*)d_in[5];
    const float* gamma      = (const float*)d_in[7];
    const float* beta       = (const float*)d_in[8];
    float*       out        = (float*)d_out;

    prep_mark_kernel<<<WF_BLOCKS + MARK_BLOCKS, 256>>>(Wv, edge_index);
    fused_v_ln_kernel<<<N_BLOCKS, THREADS>>>(x, gamma, beta, out);
}

// round 11
// speedup vs baseline: 1.1323x; 1.1299x over previous
#include <cuda_runtime.h>
#include <cuda_bf16.h>
#include <cstdint>

#define N_NODES 50000
#define N_EDGES 800000

#define M_TILE   128
#define THREADS  256
#define N_BLOCKS ((N_NODES + M_TILE - 1) / M_TILE)   // 391

// ---------------------------------------------------------------------------
// Device scratch. g_flag invariant: zero before every kernel_launch invocation
// (zero at module load; fused kernel re-zeroes its rows after use each run).
// g_Wfrag: B fragments for mma.m16n8k16, packed {bh0,bh1,bl0,bl1} per
// (kt, nt, lane). Identical for all CTAs -> L1-resident reads.
// ---------------------------------------------------------------------------
__device__ int g_flag[N_NODES];
__device__ __align__(16) uint4 g_Wfrag[8 * 16 * 32];      // 64 KB

// ---------------------------------------------------------------------------
// Blocked SW128 atom layout for a [128 x 128] bf16 tile (A staging).
// atom = 8 rows x 64 bf16 (1024B); atom index = (r>>3) + (k>>6)*16.
// ---------------------------------------------------------------------------
__host__ __device__ __forceinline__ uint32_t tile_off(int r, int k) {
    uint32_t off = ((uint32_t)((r >> 3) + ((k >> 6) << 4))) * 1024u
                 + (uint32_t)(r & 7) * 128u + (uint32_t)(k & 63) * 2u;
    return off ^ ((off >> 3) & 0x70);
}

__device__ __forceinline__ uint32_t smem_u32(const void* p) {
    uint32_t a;
    asm("{ .reg .u64 t; cvta.to.shared.u64 t, %1; cvt.u32.u64 %0, t; }" : "=r"(a) : "l"(p));
    return a;
}

__device__ __forceinline__ void mma16816(float* d, const uint32_t* a, uint32_t b0, uint32_t b1) {
    asm volatile(
        "mma.sync.aligned.m16n8k16.row.col.f32.bf16.bf16.f32 "
        "{%0,%1,%2,%3}, {%4,%5,%6,%7}, {%8,%9}, {%0,%1,%2,%3};"
        : "+f"(d[0]), "+f"(d[1]), "+f"(d[2]), "+f"(d[3])
        : "r"(a[0]), "r"(a[1]), "r"(a[2]), "r"(a[3]), "r"(b0), "r"(b1));
}

__device__ __forceinline__ void ldmx4(uint32_t* r, uint32_t addr) {
    asm volatile("ldmatrix.sync.aligned.m8n8.x4.shared.b16 {%0,%1,%2,%3}, [%4];"
                 : "=r"(r[0]), "=r"(r[1]), "=r"(r[2]), "=r"(r[3]) : "r"(addr));
}

__device__ __forceinline__ void split2(float2 v, uint32_t& hi, uint32_t& lo) {
    __nv_bfloat162 h, l;
    h.x = __float2bfloat16(v.x);
    h.y = __float2bfloat16(v.y);
    l.x = __float2bfloat16(v.x - __bfloat162float(h.x));
    l.y = __float2bfloat16(v.y - __bfloat162float(h.y));
    hi = *(uint32_t*)&h;
    lo = *(uint32_t*)&l;
}

// ---------------------------------------------------------------------------
// Kernel 1: W fragment build (blocks 0..15) + edge-dst marking (blocks 16..)
// Fragment for (kt, nt, lane): n = 8*nt + lane/4, k0 = 16*kt + 2*(lane%4);
//   bh0 = hi{Wt[n][k0], Wt[n][k0+1]}, bh1 = same at k0+8; bl* = lo parts.
// Wt[n][k] = Wv[k*128 + n].
// ---------------------------------------------------------------------------
#define WF_BLOCKS   16
#define MARK_CHUNK  (N_EDGES / 4)
#define MARK_BLOCKS ((MARK_CHUNK + 255) / 256)

__global__ void prep_mark_kernel(const float* __restrict__ Wv,
                                 const int* __restrict__ edge_index) {
    int b = blockIdx.x;
    if (b < WF_BLOCKS) {
        int idx = b * 256 + threadIdx.x;          // (kt*16+nt)*32+lane
        int lane = idx & 31;
        int nt   = (idx >> 5) & 15;
        int kt   = idx >> 9;
        int n  = 8 * nt + (lane >> 2);
        int k0 = 16 * kt + 2 * (lane & 3);

        float w00 = Wv[(size_t)k0 * 128 + n];
        float w01 = Wv[(size_t)(k0 + 1) * 128 + n];
        float w10 = Wv[(size_t)(k0 + 8) * 128 + n];
        float w11 = Wv[(size_t)(k0 + 9) * 128 + n];

        uint32_t h0, l0, h1, l1;
        split2(make_float2(w00, w01), h0, l0);
        split2(make_float2(w10, w11), h1, l1);
        g_Wfrag[idx] = make_uint4(h0, h1, l0, l1);
    } else {
        int idx = (b - WF_BLOCKS) * 256 + threadIdx.x;
        if (idx < MARK_CHUNK) {
            int4 d = ((const int4*)(edge_index + N_EDGES))[idx];
            if ((unsigned)d.x < N_NODES) g_flag[d.x] = 1;
            if ((unsigned)d.y < N_NODES) g_flag[d.y] = 1;
            if ((unsigned)d.z < N_NODES) g_flag[d.z] = 1;
            if ((unsigned)d.w < N_NODES) g_flag[d.w] = 1;
        }
    }
}

// ---------------------------------------------------------------------------
// Fused: V = x@Wv (bf16-split mma.sync; A via smem+ldmatrix, B via global
// L1-resident fragments, each feeding 2 m-tiles) -> h = x + V*flag -> LN.
// CTA = 128 rows, 256 threads = 8 warps; warp w: rows 32*(w>>1)..+31,
// column half 64*(w&1)..+63. 2 CTAs/SM.
// ---------------------------------------------------------------------------
#define SM_XHI 0
#define SM_XLO 32768
#define SM_DYN 65536

__global__ __launch_bounds__(THREADS, 2) void fused_v_ln_kernel(
    const float* __restrict__ x,
    const float* __restrict__ gamma,
    const float* __restrict__ beta,
    float* __restrict__ out)
{
    extern __shared__ char smem[];
    __shared__ float sg[128], sb[128];
    __shared__ float psum[M_TILE * 2], psq[M_TILE * 2];

    const uint32_t sbase = smem_u32(smem);
    const int tid  = threadIdx.x;
    const int w    = tid >> 5;
    const int lane = tid & 31;
    const int rw   = w >> 1;           // row group 0..3 (32 rows each)
    const int ch   = w & 1;            // column half
    const int row0 = blockIdx.x * M_TILE;

    if (tid < 128) { sg[tid] = gamma[tid]; sb[tid] = beta[tid]; }

    // Stage x tile (coalesced float4), split to bf16 hi/lo, store swizzled
#pragma unroll
    for (int i = 0; i < 16; i++) {
        int idx4 = tid + i * 256;            // 0..4095
        int r  = idx4 >> 5;
        int c4 = idx4 & 31;
        int rr = min(row0 + r, N_NODES - 1);
        float4 v = ((const float4*)x)[(size_t)rr * 32 + c4];

        uint32_t h01, l01, h23, l23;
        split2(make_float2(v.x, v.y), h01, l01);
        split2(make_float2(v.z, v.w), h23, l23);

        uint32_t off = tile_off(r, c4 << 2);
        *(uint2*)(smem + SM_XHI + off) = make_uint2(h01, h23);
        *(uint2*)(smem + SM_XLO + off) = make_uint2(l01, l23);
    }
    __syncthreads();

    // ---- A-side ldmatrix address precompute (two 16-row m-tiles) ----------
    const int selA  = lane >> 3;
    const int laneR = (lane & 7) + ((selA & 1) << 3);    // 0..15
    const int kOffA = (selA & 2) << 2;                   // 0 or 8

    const int rA0 = 32 * rw + laneR;          // m-tile 0
    const int rA1 = rA0 + 16;                 // m-tile 1
    const uint32_t rb0 = (uint32_t)(rA0 >> 3) * 1024u + (uint32_t)(rA0 & 7) * 128u;
    const uint32_t rb1 = (uint32_t)(rA1 >> 3) * 1024u + (uint32_t)(rA1 & 7) * 128u;
    const uint32_t xo0 = (uint32_t)(rA0 & 7) << 4;
    const uint32_t xo1 = (uint32_t)(rA1 & 7) << 4;

    // B fragment pointer: g_Wfrag[(kt*16 + 8*ch + nt)*32 + lane]
    const uint4* fragp = g_Wfrag + (8 * ch) * 32 + lane;

    float acc[2][8][4];
#pragma unroll
    for (int mt = 0; mt < 2; mt++)
#pragma unroll
        for (int nt = 0; nt < 8; nt++)
#pragma unroll
            for (int i = 0; i < 4; i++) acc[mt][nt][i] = 0.0f;

#pragma unroll
    for (int kt = 0; kt < 8; kt++) {
        const int kk = 16 * kt + kOffA;
        const uint32_t katom = (uint32_t)((kk >> 6) << 14);
        const uint32_t klow  = (uint32_t)((kk & 63) * 2);
        const uint32_t o0 = rb0 + katom + (klow ^ xo0);
        const uint32_t o1 = rb1 + katom + (klow ^ xo1);

        uint32_t ah0[4], al0[4], ah1[4], al1[4];
        ldmx4(ah0, sbase + SM_XHI + o0);
        ldmx4(al0, sbase + SM_XLO + o0);
        ldmx4(ah1, sbase + SM_XHI + o1);
        ldmx4(al1, sbase + SM_XLO + o1);

        const uint4* fk = fragp + kt * 512;
#pragma unroll
        for (int nt = 0; nt < 8; nt++) {
            uint4 f = __ldg(fk + nt * 32);     // {bh0, bh1, bl0, bl1}
            mma16816(acc[0][nt], ah0, f.x, f.y);
            mma16816(acc[0][nt], ah0, f.z, f.w);
            mma16816(acc[0][nt], al0, f.x, f.y);
            mma16816(acc[1][nt], ah1, f.x, f.y);
            mma16816(acc[1][nt], ah1, f.z, f.w);
            mma16816(acc[1][nt], al1, f.x, f.y);
        }
    }

    // ---- epilogue ---------------------------------------------------------
    // Thread owns rows (per mt): r = 32*rw + 16*mt + g and r+8;
    // cols 64*ch + 8*nt + 2*t.
    const int g = lane >> 2;
    const int t = lane & 3;

    float mus[2][2], invs[2][2];

    // Pass 1: h = x + V*flag, row sums
#pragma unroll
    for (int mt = 0; mt < 2; mt++) {
        const int r0 = 32 * rw + 16 * mt + g;
        const int r1 = r0 + 8;
        const int rc0 = min(row0 + r0, N_NODES - 1);
        const int rc1 = min(row0 + r1, N_NODES - 1);
        const float fac0 = (float)g_flag[rc0];
        const float fac1 = (float)g_flag[rc1];

        float s0 = 0.0f, s1 = 0.0f;
#pragma unroll
        for (int nt = 0; nt < 8; nt++) {
            const int c = 64 * ch + 8 * nt + 2 * t;
            float2 x0 = *(const float2*)(x + (size_t)rc0 * 128 + c);
            float2 x1 = *(const float2*)(x + (size_t)rc1 * 128 + c);
            float h00 = fmaf(acc[mt][nt][0], fac0, x0.x);
            float h01 = fmaf(acc[mt][nt][1], fac0, x0.y);
            float h10 = fmaf(acc[mt][nt][2], fac1, x1.x);
            float h11 = fmaf(acc[mt][nt][3], fac1, x1.y);
            acc[mt][nt][0] = h00; acc[mt][nt][1] = h01;
            acc[mt][nt][2] = h10; acc[mt][nt][3] = h11;
            s0 += h00 + h01;
            s1 += h10 + h11;
        }
        s0 += __shfl_xor_sync(0xffffffffu, s0, 1);
        s0 += __shfl_xor_sync(0xffffffffu, s0, 2);
        s1 += __shfl_xor_sync(0xffffffffu, s1, 1);
        s1 += __shfl_xor_sync(0xffffffffu, s1, 2);
        if (t == 0) { psum[r0 * 2 + ch] = s0; psum[r1 * 2 + ch] = s1; }
    }
    __syncthreads();

    // re-zero flags for next graph replay (all facs of this CTA already read)
    if (tid < M_TILE) {
        int rz = row0 + tid;
        if (rz < N_NODES) g_flag[rz] = 0;
    }

    // Pass 2: variances
#pragma unroll
    for (int mt = 0; mt < 2; mt++) {
        const int r0 = 32 * rw + 16 * mt + g;
        const int r1 = r0 + 8;
        const float mu0 = (psum[r0 * 2] + psum[r0 * 2 + 1]) * (1.0f / 128.0f);
        const float mu1 = (psum[r1 * 2] + psum[r1 * 2 + 1]) * (1.0f / 128.0f);
        mus[mt][0] = mu0; mus[mt][1] = mu1;

        float q0 = 0.0f, q1 = 0.0f;
#pragma unroll
        for (int nt = 0; nt < 8; nt++) {
            float d00 = acc[mt][nt][0] - mu0, d01 = acc[mt][nt][1] - mu0;
            float d10 = acc[mt][nt][2] - mu1, d11 = acc[mt][nt][3] - mu1;
            q0 = fmaf(d00, d00, fmaf(d01, d01, q0));
            q1 = fmaf(d10, d10, fmaf(d11, d11, q1));
        }
        q0 += __shfl_xor_sync(0xffffffffu, q0, 1);
        q0 += __shfl_xor_sync(0xffffffffu, q0, 2);
        q1 += __shfl_xor_sync(0xffffffffu, q1, 1);
        q1 += __shfl_xor_sync(0xffffffffu, q1, 2);
        if (t == 0) { psq[r0 * 2 + ch] = q0; psq[r1 * 2 + ch] = q1; }
    }
    __syncthreads();

    // Pass 3: normalize + store
#pragma unroll
    for (int mt = 0; mt < 2; mt++) {
        const int r0 = 32 * rw + 16 * mt + g;
        const int r1 = r0 + 8;
        invs[mt][0] = rsqrtf((psq[r0 * 2] + psq[r0 * 2 + 1]) * (1.0f / 128.0f) + 1e-5f);
        invs[mt][1] = rsqrtf((psq[r1 * 2] + psq[r1 * 2 + 1]) * (1.0f / 128.0f) + 1e-5f);

        const int row0g = row0 + r0;
        const int row1g = row0 + r1;
        const float mu0 = mus[mt][0], mu1 = mus[mt][1];
        const float inv0 = invs[mt][0], inv1 = invs[mt][1];

#pragma unroll
        for (int nt = 0; nt < 8; nt++) {
            const int c = 64 * ch + 8 * nt + 2 * t;
            float2 gm = *(const float2*)(sg + c);
            float2 bt = *(const float2*)(sb + c);
            if (row0g < N_NODES) {
                float2 o;
                o.x = fmaf((acc[mt][nt][0] - mu0) * inv0, gm.x, bt.x);
                o.y = fmaf((acc[mt][nt][1] - mu0) * inv0, gm.y, bt.y);
                *(float2*)(out + (size_t)row0g * 128 + c) = o;
            }
            if (row1g < N_NODES) {
                float2 o;
                o.x = fmaf((acc[mt][nt][2] - mu1) * inv1, gm.x, bt.x);
                o.y = fmaf((acc[mt][nt][3] - mu1) * inv1, gm.y, bt.y);
                *(float2*)(out + (size_t)row1g * 128 + c) = o;
            }
        }
    }
}

// ---------------------------------------------------------------------------
extern "C" void kernel_launch(void* const* d_in, const int* in_sizes, int n_in,
                              void* d_out, int out_size)
{
    const float* x          = (const float*)d_in[0];
    const int*   edge_index = (const int*)d_in[1];
    const float* Wv         = (const float*)d_in[5];
    const float* gamma      = (const float*)d_in[7];
    const float* beta       = (const float*)d_in[8];
    float*       out        = (float*)d_out;

    cudaFuncSetAttribute(fused_v_ln_kernel,
                         cudaFuncAttributeMaxDynamicSharedMemorySize, SM_DYN);

    prep_mark_kernel<<<WF_BLOCKS + MARK_BLOCKS, 256>>>(Wv, edge_index);
    fused_v_ln_kernel<<<N_BLOCKS, THREADS, SM_DYN>>>(x, gamma, beta, out);
}

// round 13
// speedup vs baseline: 1.1489x; 1.0146x over previous
#include <cuda_runtime.h>
#include <cuda_bf16.h>
#include <cstdint>

#define N_NODES 50000
#define N_EDGES 800000

#define M_TILE   128
#define THREADS  256
#define N_BLOCKS ((N_NODES + M_TILE - 1) / M_TILE)   // 391

// ---------------------------------------------------------------------------
// Device scratch. g_flag invariant: zero before every kernel_launch invocation
// (zero at module load; fused kernel re-zeroes its rows after use each run).
// g_Wfrag: B fragments for mma.m16n8k16, packed {bh0,bh1,bl0,bl1} per
// (kt, nt, lane). Identical for all CTAs -> L1-resident reads.
// ---------------------------------------------------------------------------
__device__ int g_flag[N_NODES];
__device__ __align__(16) uint4 g_Wfrag[8 * 16 * 32];      // 64 KB

// ---------------------------------------------------------------------------
// Blocked SW128 atom layout for a [128 x 128] bf16 tile (A staging).
// atom = 8 rows x 64 bf16 (1024B); atom index = (r>>3) + (k>>6)*16.
// ---------------------------------------------------------------------------
__host__ __device__ __forceinline__ uint32_t tile_off(int r, int k) {
    uint32_t off = ((uint32_t)((r >> 3) + ((k >> 6) << 4))) * 1024u
                 + (uint32_t)(r & 7) * 128u + (uint32_t)(k & 63) * 2u;
    return off ^ ((off >> 3) & 0x70);
}

__device__ __forceinline__ uint32_t smem_u32(const void* p) {
    uint32_t a;
    asm("{ .reg .u64 t; cvta.to.shared.u64 t, %1; cvt.u32.u64 %0, t; }" : "=r"(a) : "l"(p));
    return a;
}

__device__ __forceinline__ void mma16816(float* d, const uint32_t* a, uint32_t b0, uint32_t b1) {
    asm volatile(
        "mma.sync.aligned.m16n8k16.row.col.f32.bf16.bf16.f32 "
        "{%0,%1,%2,%3}, {%4,%5,%6,%7}, {%8,%9}, {%0,%1,%2,%3};"
        : "+f"(d[0]), "+f"(d[1]), "+f"(d[2]), "+f"(d[3])
        : "r"(a[0]), "r"(a[1]), "r"(a[2]), "r"(a[3]), "r"(b0), "r"(b1));
}

__device__ __forceinline__ void ldmx4(uint32_t* r, uint32_t addr) {
    asm volatile("ldmatrix.sync.aligned.m8n8.x4.shared.b16 {%0,%1,%2,%3}, [%4];"
                 : "=r"(r[0]), "=r"(r[1]), "=r"(r[2]), "=r"(r[3]) : "r"(addr));
}

__device__ __forceinline__ void split2(float2 v, uint32_t& hi, uint32_t& lo) {
    __nv_bfloat162 h, l;
    h.x = __float2bfloat16(v.x);
    h.y = __float2bfloat16(v.y);
    l.x = __float2bfloat16(v.x - __bfloat162float(h.x));
    l.y = __float2bfloat16(v.y - __bfloat162float(h.y));
    hi = *(uint32_t*)&h;
    lo = *(uint32_t*)&l;
}

__device__ __forceinline__ float2 bf2sum(uint32_t h, uint32_t l) {
    __nv_bfloat162 hb = *(__nv_bfloat162*)&h;
    __nv_bfloat162 lb = *(__nv_bfloat162*)&l;
    return make_float2(__bfloat162float(hb.x) + __bfloat162float(lb.x),
                       __bfloat162float(hb.y) + __bfloat162float(lb.y));
}

// ---------------------------------------------------------------------------
// Kernel 1: W fragment build (blocks 0..15) + edge-dst marking (blocks 16..)
// ---------------------------------------------------------------------------
#define WF_BLOCKS   16
#define MARK_CHUNK  (N_EDGES / 4)
#define MARK_BLOCKS ((MARK_CHUNK + 255) / 256)

__global__ void prep_mark_kernel(const float* __restrict__ Wv,
                                 const int* __restrict__ edge_index) {
    int b = blockIdx.x;
    if (b < WF_BLOCKS) {
        int idx = b * 256 + threadIdx.x;          // (kt*16+nt)*32+lane
        int lane = idx & 31;
        int nt   = (idx >> 5) & 15;
        int kt   = idx >> 9;
        int n  = 8 * nt + (lane >> 2);
        int k0 = 16 * kt + 2 * (lane & 3);

        float w00 = Wv[(size_t)k0 * 128 + n];
        float w01 = Wv[(size_t)(k0 + 1) * 128 + n];
        float w10 = Wv[(size_t)(k0 + 8) * 128 + n];
        float w11 = Wv[(size_t)(k0 + 9) * 128 + n];

        uint32_t h0, l0, h1, l1;
        split2(make_float2(w00, w01), h0, l0);
        split2(make_float2(w10, w11), h1, l1);
        g_Wfrag[idx] = make_uint4(h0, h1, l0, l1);
    } else {
        int idx = (b - WF_BLOCKS) * 256 + threadIdx.x;
        if (idx < MARK_CHUNK) {
            int4 d = ((const int4*)(edge_index + N_EDGES))[idx];
            if ((unsigned)d.x < N_NODES) g_flag[d.x] = 1;
            if ((unsigned)d.y < N_NODES) g_flag[d.y] = 1;
            if ((unsigned)d.z < N_NODES) g_flag[d.z] = 1;
            if ((unsigned)d.w < N_NODES) g_flag[d.w] = 1;
        }
    }
}

// ---------------------------------------------------------------------------
// Fused: V = x@Wv (bf16-split mma.sync; A via smem+ldmatrix, B via global
// L1-resident fragments; product-major mma scheduling, 8-deep independent
// chains) -> h = x + V*flag -> LayerNorm.
// CTA = 128 rows, 256 threads = 8 warps; warp w: rows 32*(w>>1)..+31,
// column half 64*(w&1)..+63. 2 CTAs/SM.
// ---------------------------------------------------------------------------
#define SM_XHI 0
#define SM_XLO 32768
#define SM_DYN 65536

__global__ __launch_bounds__(THREADS, 2) void fused_v_ln_kernel(
    const float* __restrict__ x,
    const float* __restrict__ gamma,
    const float* __restrict__ beta,
    float* __restrict__ out)
{
    extern __shared__ char smem[];
    __shared__ float sg[128], sb[128];
    __shared__ float psum[M_TILE * 2], psq[M_TILE * 2];

    const uint32_t sbase = smem_u32(smem);
    const int tid  = threadIdx.x;
    const int w    = tid >> 5;
    const int lane = tid & 31;
    const int rw   = w >> 1;           // row group 0..3 (32 rows each)
    const int ch   = w & 1;            // column half
    const int row0 = blockIdx.x * M_TILE;

    if (tid < 128) { sg[tid] = gamma[tid]; sb[tid] = beta[tid]; }

    // Stage x tile (coalesced float4), split to bf16 hi/lo, store swizzled
#pragma unroll
    for (int i = 0; i < 16; i++) {
        int idx4 = tid + i * 256;            // 0..4095
        int r  = idx4 >> 5;
        int c4 = idx4 & 31;
        int rr = min(row0 + r, N_NODES - 1);
        float4 v = ((const float4*)x)[(size_t)rr * 32 + c4];

        uint32_t h01, l01, h23, l23;
        split2(make_float2(v.x, v.y), h01, l01);
        split2(make_float2(v.z, v.w), h23, l23);

        uint32_t off = tile_off(r, c4 << 2);
        *(uint2*)(smem + SM_XHI + off) = make_uint2(h01, h23);
        *(uint2*)(smem + SM_XLO + off) = make_uint2(l01, l23);
    }
    __syncthreads();

    // ---- A-side ldmatrix address precompute (two 16-row m-tiles) ----------
    const int selA  = lane >> 3;
    const int laneR = (lane & 7) + ((selA & 1) << 3);    // 0..15
    const int kOffA = (selA & 2) << 2;                   // 0 or 8

    const int rA0 = 32 * rw + laneR;          // m-tile 0
    const int rA1 = rA0 + 16;                 // m-tile 1
    const uint32_t rb0 = (uint32_t)(rA0 >> 3) * 1024u + (uint32_t)(rA0 & 7) * 128u;
    const uint32_t rb1 = (uint32_t)(rA1 >> 3) * 1024u + (uint32_t)(rA1 & 7) * 128u;
    const uint32_t xo0 = (uint32_t)(rA0 & 7) << 4;
    const uint32_t xo1 = (uint32_t)(rA1 & 7) << 4;

    // B fragment pointer: g_Wfrag[(kt*16 + 8*ch + nt)*32 + lane]
    const uint4* fragp = g_Wfrag + (8 * ch) * 32 + lane;

    float acc[2][8][4];
#pragma unroll
    for (int mt = 0; mt < 2; mt++)
#pragma unroll
        for (int nt = 0; nt < 8; nt++)
#pragma unroll
            for (int i = 0; i < 4; i++) acc[mt][nt][i] = 0.0f;

#pragma unroll
    for (int kt = 0; kt < 8; kt++) {
        const int kk = 16 * kt + kOffA;
        const uint32_t katom = (uint32_t)((kk >> 6) << 14);
        const uint32_t klow  = (uint32_t)((kk & 63) * 2);
        const uint32_t o0 = rb0 + katom + (klow ^ xo0);
        const uint32_t o1 = rb1 + katom + (klow ^ xo1);

        uint32_t ah0[4], al0[4], ah1[4], al1[4];
        ldmx4(ah0, sbase + SM_XHI + o0);
        ldmx4(al0, sbase + SM_XLO + o0);
        ldmx4(ah1, sbase + SM_XHI + o1);
        ldmx4(al1, sbase + SM_XLO + o1);

        const uint4* fk = fragp + kt * 512;
#pragma unroll
        for (int h = 0; h < 2; h++) {
            // Batch-load 4 B fragments (16 regs), then product-major passes:
            // each acc is touched at issue distance 8 -> no RAW stalls.
            uint4 f0 = __ldg(fk + (4 * h + 0) * 32);
            uint4 f1 = __ldg(fk + (4 * h + 1) * 32);
            uint4 f2 = __ldg(fk + (4 * h + 2) * 32);
            uint4 f3 = __ldg(fk + (4 * h + 3) * 32);
            const int n0 = 4 * h;

            // pass 0: hi * Whi
            mma16816(acc[0][n0 + 0], ah0, f0.x, f0.y);
            mma16816(acc[0][n0 + 1], ah0, f1.x, f1.y);
            mma16816(acc[0][n0 + 2], ah0, f2.x, f2.y);
            mma16816(acc[0][n0 + 3], ah0, f3.x, f3.y);
            mma16816(acc[1][n0 + 0], ah1, f0.x, f0.y);
            mma16816(acc[1][n0 + 1], ah1, f1.x, f1.y);
            mma16816(acc[1][n0 + 2], ah1, f2.x, f2.y);
            mma16816(acc[1][n0 + 3], ah1, f3.x, f3.y);
            // pass 1: hi * Wlo
            mma16816(acc[0][n0 + 0], ah0, f0.z, f0.w);
            mma16816(acc[0][n0 + 1], ah0, f1.z, f1.w);
            mma16816(acc[0][n0 + 2], ah0, f2.z, f2.w);
            mma16816(acc[0][n0 + 3], ah0, f3.z, f3.w);
            mma16816(acc[1][n0 + 0], ah1, f0.z, f0.w);
            mma16816(acc[1][n0 + 1], ah1, f1.z, f1.w);
            mma16816(acc[1][n0 + 2], ah1, f2.z, f2.w);
            mma16816(acc[1][n0 + 3], ah1, f3.z, f3.w);
            // pass 2: lo * Whi
            mma16816(acc[0][n0 + 0], al0, f0.x, f0.y);
            mma16816(acc[0][n0 + 1], al0, f1.x, f1.y);
            mma16816(acc[0][n0 + 2], al0, f2.x, f2.y);
            mma16816(acc[0][n0 + 3], al0, f3.x, f3.y);
            mma16816(acc[1][n0 + 0], al1, f0.x, f0.y);
            mma16816(acc[1][n0 + 1], al1, f1.x, f1.y);
            mma16816(acc[1][n0 + 2], al1, f2.x, f2.y);
            mma16816(acc[1][n0 + 3], al1, f3.x, f3.y);
        }
    }

    // ---- epilogue ---------------------------------------------------------
    // Thread owns rows (per mt): r = 32*rw + 16*mt + g and r+8;
    // cols c = 64*ch + 8*nt + 2*t. x reconstructed from smem hi+lo
    // (exact to ~2^-19): conflict-free LDS instead of scattered gmem reads.
    const int g = lane >> 2;
    const int t = lane & 3;
    const uint32_t cxor = (uint32_t)(4 * t);            // (c&63)*2 base for nt=0

    float mus[2][2];

    // Pass 1: h = x + V*flag, row sums
#pragma unroll
    for (int mt = 0; mt < 2; mt++) {
        const int r0 = 32 * rw + 16 * mt + g;
        const int r1 = r0 + 8;
        const int rc0 = min(row0 + r0, N_NODES - 1);
        const int rc1 = min(row0 + r1, N_NODES - 1);
        const float fac0 = (float)g_flag[rc0];
        const float fac1 = (float)g_flag[rc1];

        const uint32_t rbe0 = (uint32_t)(r0 >> 3) * 1024u + (uint32_t)(r0 & 7) * 128u
                            + ((uint32_t)ch << 14);
        const uint32_t rbe1 = (uint32_t)(r1 >> 3) * 1024u + (uint32_t)(r1 & 7) * 128u
                            + ((uint32_t)ch << 14);
        const uint32_t xe0 = (uint32_t)(r0 & 7) << 4;
        const uint32_t xe1 = (uint32_t)(r1 & 7) << 4;

        float s0 = 0.0f, s1 = 0.0f;
#pragma unroll
        for (int nt = 0; nt < 8; nt++) {
            const uint32_t cl = (uint32_t)(16 * nt) + cxor;     // (c&63)*2
            const uint32_t off0 = rbe0 + (cl ^ xe0);
            const uint32_t off1 = rbe1 + (cl ^ xe1);
            uint32_t xh0 = *(const uint32_t*)(smem + SM_XHI + off0);
            uint32_t xl0 = *(const uint32_t*)(smem + SM_XLO + off0);
            uint32_t xh1 = *(const uint32_t*)(smem + SM_XHI + off1);
            uint32_t xl1 = *(const uint32_t*)(smem + SM_XLO + off1);
            float2 x0 = bf2sum(xh0, xl0);
            float2 x1 = bf2sum(xh1, xl1);

            float h00 = fmaf(acc[mt][nt][0], fac0, x0.x);
            float h01 = fmaf(acc[mt][nt][1], fac0, x0.y);
            float h10 = fmaf(acc[mt][nt][2], fac1, x1.x);
            float h11 = fmaf(acc[mt][nt][3], fac1, x1.y);
            acc[mt][nt][0] = h00; acc[mt][nt][1] = h01;
            acc[mt][nt][2] = h10; acc[mt][nt][3] = h11;
            s0 += h00 + h01;
            s1 += h10 + h11;
        }
        s0 += __shfl_xor_sync(0xffffffffu, s0, 1);
        s0 += __shfl_xor_sync(0xffffffffu, s0, 2);
        s1 += __shfl_xor_sync(0xffffffffu, s1, 1);
        s1 += __shfl_xor_sync(0xffffffffu, s1, 2);
        if (t == 0) { psum[r0 * 2 + ch] = s0; psum[r1 * 2 + ch] = s1; }
    }
    __syncthreads();

    // re-zero flags for next graph replay (all facs of this CTA already read)
    if (tid < M_TILE) {
        int rz = row0 + tid;
        if (rz < N_NODES) g_flag[rz] = 0;
    }

    // Pass 2: variances
#pragma unroll
    for (int mt = 0; mt < 2; mt++) {
        const int r0 = 32 * rw + 16 * mt + g;
        const int r1 = r0 + 8;
        const float mu0 = (psum[r0 * 2] + psum[r0 * 2 + 1]) * (1.0f / 128.0f);
        const float mu1 = (psum[r1 * 2] + psum[r1 * 2 + 1]) * (1.0f / 128.0f);
        mus[mt][0] = mu0; mus[mt][1] = mu1;

        float q0 = 0.0f, q1 = 0.0f;
#pragma unroll
        for (int nt = 0; nt < 8; nt++) {
            float d00 = acc[mt][nt][0] - mu0, d01 = acc[mt][nt][1] - mu0;
            float d10 = acc[mt][nt][2] - mu1, d11 = acc[mt][nt][3] - mu1;
            q0 = fmaf(d00, d00, fmaf(d01, d01, q0));
            q1 = fmaf(d10, d10, fmaf(d11, d11, q1));
        }
        q0 += __shfl_xor_sync(0xffffffffu, q0, 1);
        q0 += __shfl_xor_sync(0xffffffffu, q0, 2);
        q1 += __shfl_xor_sync(0xffffffffu, q1, 1);
        q1 += __shfl_xor_sync(0xffffffffu, q1, 2);
        if (t == 0) { psq[r0 * 2 + ch] = q0; psq[r1 * 2 + ch] = q1; }
    }
    __syncthreads();

    // Pass 3: normalize + store
#pragma unroll
    for (int mt = 0; mt < 2; mt++) {
        const int r0 = 32 * rw + 16 * mt + g;
        const int r1 = r0 + 8;
        const float inv0 = rsqrtf((psq[r0 * 2] + psq[r0 * 2 + 1]) * (1.0f / 128.0f) + 1e-5f);
        const float inv1 = rsqrtf((psq[r1 * 2] + psq[r1 * 2 + 1]) * (1.0f / 128.0f) + 1e-5f);

        const int row0g = row0 + r0;
        const int row1g = row0 + r1;
        const float mu0 = mus[mt][0], mu1 = mus[mt][1];

#pragma unroll
        for (int nt = 0; nt < 8; nt++) {
            const int c = 64 * ch + 8 * nt + 2 * t;
            float2 gm = *(const float2*)(sg + c);
            float2 bt = *(const float2*)(sb + c);
            if (row0g < N_NODES) {
                float2 o;
                o.x = fmaf((acc[mt][nt][0] - mu0) * inv0, gm.x, bt.x);
                o.y = fmaf((acc[mt][nt][1] - mu0) * inv0, gm.y, bt.y);
                *(float2*)(out + (size_t)row0g * 128 + c) = o;
            }
            if (row1g < N_NODES) {
                float2 o;
                o.x = fmaf((acc[mt][nt][2] - mu1) * inv1, gm.x, bt.x);
                o.y = fmaf((acc[mt][nt][3] - mu1) * inv1, gm.y, bt.y);
                *(float2*)(out + (size_t)row1g * 128 + c) = o;
            }
        }
    }
}

// ---------------------------------------------------------------------------
extern "C" void kernel_launch(void* const* d_in, const int* in_sizes, int n_in,
                              void* d_out, int out_size)
{
    const float* x          = (const float*)d_in[0];
    const int*   edge_index = (const int*)d_in[1];
    const float* Wv         = (const float*)d_in[5];
    const float* gamma      = (const float*)d_in[7];
    const float* beta       = (const float*)d_in[8];
    float*       out        = (float*)d_out;

    cudaFuncSetAttribute(fused_v_ln_kernel,
                         cudaFuncAttributeMaxDynamicSharedMemorySize, SM_DYN);

    prep_mark_kernel<<<WF_BLOCKS + MARK_BLOCKS, 256>>>(Wv, edge_index);
    fused_v_ln_kernel<<<N_BLOCKS, THREADS, SM_DYN>>>(x, gamma, beta, out);
}

// round 16
// speedup vs baseline: 1.1641x; 1.0132x over previous
#include <cuda_runtime.h>
#include <cuda_bf16.h>
#include <cstdint>

#define N_NODES 50000
#define N_EDGES 800000

#define M_TILE   64
#define THREADS  128
#define N_BLOCKS ((N_NODES + M_TILE - 1) / M_TILE)   // 782

// ---------------------------------------------------------------------------
// Device scratch. g_flag invariant: zero before every kernel_launch invocation
// (zero at module load; fused kernel re-zeroes its rows after use each run).
// g_Wfrag: B fragments for mma.m16n8k16, packed {bh0,bh1,bl0,bl1} per
// (kt, nt, lane). Identical for all CTAs -> L1-resident reads.
// ---------------------------------------------------------------------------
__device__ int g_flag[N_NODES];
__device__ __align__(16) uint4 g_Wfrag[8 * 16 * 32];      // 64 KB

// ---------------------------------------------------------------------------
// Blocked SW128 atom layout for a [64 x 128] bf16 tile (A staging).
// atom = 8 rows x 64 bf16 (1024B); atom index = (r>>3) + (k>>6)*8.
// ---------------------------------------------------------------------------
__host__ __device__ __forceinline__ uint32_t tile_off(int r, int k) {
    uint32_t off = ((uint32_t)((r >> 3) + ((k >> 6) << 3))) * 1024u
                 + (uint32_t)(r & 7) * 128u + (uint32_t)(k & 63) * 2u;
    return off ^ ((off >> 3) & 0x70);
}

__device__ __forceinline__ uint32_t smem_u32(const void* p) {
    uint32_t a;
    asm("{ .reg .u64 t; cvta.to.shared.u64 t, %1; cvt.u32.u64 %0, t; }" : "=r"(a) : "l"(p));
    return a;
}

__device__ __forceinline__ void mma16816(float* d, const uint32_t* a, uint32_t b0, uint32_t b1) {
    asm volatile(
        "mma.sync.aligned.m16n8k16.row.col.f32.bf16.bf16.f32 "
        "{%0,%1,%2,%3}, {%4,%5,%6,%7}, {%8,%9}, {%0,%1,%2,%3};"
        : "+f"(d[0]), "+f"(d[1]), "+f"(d[2]), "+f"(d[3])
        : "r"(a[0]), "r"(a[1]), "r"(a[2]), "r"(a[3]), "r"(b0), "r"(b1));
}

__device__ __forceinline__ void ldmx4(uint32_t* r, uint32_t addr) {
    asm volatile("ldmatrix.sync.aligned.m8n8.x4.shared.b16 {%0,%1,%2,%3}, [%4];"
                 : "=r"(r[0]), "=r"(r[1]), "=r"(r[2]), "=r"(r[3]) : "r"(addr));
}

__device__ __forceinline__ void split2(float2 v, uint32_t& hi, uint32_t& lo) {
    __nv_bfloat162 h, l;
    h.x = __float2bfloat16(v.x);
    h.y = __float2bfloat16(v.y);
    l.x = __float2bfloat16(v.x - __bfloat162float(h.x));
    l.y = __float2bfloat16(v.y - __bfloat162float(h.y));
    hi = *(uint32_t*)&h;
    lo = *(uint32_t*)&l;
}

__device__ __forceinline__ float2 bf2sum(uint32_t h, uint32_t l) {
    __nv_bfloat162 hb = *(__nv_bfloat162*)&h;
    __nv_bfloat162 lb = *(__nv_bfloat162*)&l;
    return make_float2(__bfloat162float(hb.x) + __bfloat162float(lb.x),
                       __bfloat162float(hb.y) + __bfloat162float(lb.y));
}

// ---------------------------------------------------------------------------
// Kernel 1: W fragment build (blocks 0..15) + edge-dst marking (blocks 16..)
// ---------------------------------------------------------------------------
#define WF_BLOCKS   16
#define MARK_CHUNK  (N_EDGES / 4)
#define MARK_BLOCKS ((MARK_CHUNK + 255) / 256)

__global__ void prep_mark_kernel(const float* __restrict__ Wv,
                                 const int* __restrict__ edge_index) {
    int b = blockIdx.x;
    if (b < WF_BLOCKS) {
        int idx = b * 256 + threadIdx.x;          // (kt*16+nt)*32+lane
        int lane = idx & 31;
        int nt   = (idx >> 5) & 15;
        int kt   = idx >> 9;
        int n  = 8 * nt + (lane >> 2);
        int k0 = 16 * kt + 2 * (lane & 3);

        float w00 = Wv[(size_t)k0 * 128 + n];
        float w01 = Wv[(size_t)(k0 + 1) * 128 + n];
        float w10 = Wv[(size_t)(k0 + 8) * 128 + n];
        float w11 = Wv[(size_t)(k0 + 9) * 128 + n];

        uint32_t h0, l0, h1, l1;
        split2(make_float2(w00, w01), h0, l0);
        split2(make_float2(w10, w11), h1, l1);
        g_Wfrag[idx] = make_uint4(h0, h1, l0, l1);
    } else {
        int idx = (b - WF_BLOCKS) * 256 + threadIdx.x;
        if (idx < MARK_CHUNK) {
            int4 d = ((const int4*)(edge_index + N_EDGES))[idx];
            if ((unsigned)d.x < N_NODES) g_flag[d.x] = 1;
            if ((unsigned)d.y < N_NODES) g_flag[d.y] = 1;
            if ((unsigned)d.z < N_NODES) g_flag[d.z] = 1;
            if ((unsigned)d.w < N_NODES) g_flag[d.w] = 1;
        }
    }
}

// ---------------------------------------------------------------------------
// Fused: V = x@Wv (bf16-split mma.sync; A via smem+ldmatrix, B via global
// L1-resident fragments; product-major mma scheduling) -> h = x + V*flag
// -> single-pass LayerNorm.
// CTA = 64 rows, 128 threads = 4 warps; warp w: rows 32*(w>>1)..+31,
// column half 64*(w&1)..+63. 4 CTAs/SM for phase-decorrelated overlap.
// ---------------------------------------------------------------------------
#define SM_XHI 0
#define SM_XLO 16384
#define SM_DYN 32768

__global__ __launch_bounds__(THREADS, 4) void fused_v_ln_kernel(
    const float* __restrict__ x,
    const float* __restrict__ gamma,
    const float* __restrict__ beta,
    float* __restrict__ out)
{
    extern __shared__ char smem[];
    __shared__ float sg[128], sb[128];
    __shared__ float psum[M_TILE * 2], psq[M_TILE * 2];

    const uint32_t sbase = smem_u32(smem);
    const int tid  = threadIdx.x;
    const int w    = tid >> 5;
    const int lane = tid & 31;
    const int rw   = w >> 1;           // row group 0..1 (32 rows each)
    const int ch   = w & 1;            // column half
    const int row0 = blockIdx.x * M_TILE;

    sg[tid] = gamma[tid];
    sb[tid] = beta[tid];

    // Stage x tile (coalesced float4), split to bf16 hi/lo, store swizzled
#pragma unroll
    for (int i = 0; i < 16; i++) {
        int idx4 = tid + i * 128;            // 0..2047
        int r  = idx4 >> 5;
        int c4 = idx4 & 31;
        int rr = min(row0 + r, N_NODES - 1);
        float4 v = ((const float4*)x)[(size_t)rr * 32 + c4];

        uint32_t h01, l01, h23, l23;
        split2(make_float2(v.x, v.y), h01, l01);
        split2(make_float2(v.z, v.w), h23, l23);

        uint32_t off = tile_off(r, c4 << 2);
        *(uint2*)(smem + SM_XHI + off) = make_uint2(h01, h23);
        *(uint2*)(smem + SM_XLO + off) = make_uint2(l01, l23);
    }
    __syncthreads();

    // ---- A-side ldmatrix address precompute (two 16-row m-tiles) ----------
    const int selA  = lane >> 3;
    const int laneR = (lane & 7) + ((selA & 1) << 3);    // 0..15
    const int kOffA = (selA & 2) << 2;                   // 0 or 8

    const int rA0 = 32 * rw + laneR;          // m-tile 0
    const int rA1 = rA0 + 16;                 // m-tile 1
    const uint32_t rb0 = (uint32_t)(rA0 >> 3) * 1024u + (uint32_t)(rA0 & 7) * 128u;
    const uint32_t rb1 = (uint32_t)(rA1 >> 3) * 1024u + (uint32_t)(rA1 & 7) * 128u;
    const uint32_t xo0 = (uint32_t)(rA0 & 7) << 4;
    const uint32_t xo1 = (uint32_t)(rA1 & 7) << 4;

    // B fragment pointer: g_Wfrag[(kt*16 + 8*ch + nt)*32 + lane]
    const uint4* fragp = g_Wfrag + (8 * ch) * 32 + lane;

    float acc[2][8][4];
#pragma unroll
    for (int mt = 0; mt < 2; mt++)
#pragma unroll
        for (int nt = 0; nt < 8; nt++)
#pragma unroll
            for (int i = 0; i < 4; i++) acc[mt][nt][i] = 0.0f;

#pragma unroll
    for (int kt = 0; kt < 8; kt++) {
        const int kk = 16 * kt + kOffA;
        const uint32_t katom = (uint32_t)((kk >> 6) << 13);
        const uint32_t klow  = (uint32_t)((kk & 63) * 2);
        const uint32_t o0 = rb0 + katom + (klow ^ xo0);
        const uint32_t o1 = rb1 + katom + (klow ^ xo1);

        uint32_t ah0[4], al0[4], ah1[4], al1[4];
        ldmx4(ah0, sbase + SM_XHI + o0);
        ldmx4(al0, sbase + SM_XLO + o0);
        ldmx4(ah1, sbase + SM_XHI + o1);
        ldmx4(al1, sbase + SM_XLO + o1);

        const uint4* fk = fragp + kt * 512;
#pragma unroll
        for (int h = 0; h < 2; h++) {
            // Batch-load 4 B fragments, product-major passes:
            // each acc touched at issue distance 8 -> no RAW stalls.
            uint4 f0 = __ldg(fk + (4 * h + 0) * 32);
            uint4 f1 = __ldg(fk + (4 * h + 1) * 32);
            uint4 f2 = __ldg(fk + (4 * h + 2) * 32);
            uint4 f3 = __ldg(fk + (4 * h + 3) * 32);
            const int n0 = 4 * h;

            // pass 0: hi * Whi
            mma16816(acc[0][n0 + 0], ah0, f0.x, f0.y);
            mma16816(acc[0][n0 + 1], ah0, f1.x, f1.y);
            mma16816(acc[0][n0 + 2], ah0, f2.x, f2.y);
            mma16816(acc[0][n0 + 3], ah0, f3.x, f3.y);
            mma16816(acc[1][n0 + 0], ah1, f0.x, f0.y);
            mma16816(acc[1][n0 + 1], ah1, f1.x, f1.y);
            mma16816(acc[1][n0 + 2], ah1, f2.x, f2.y);
            mma16816(acc[1][n0 + 3], ah1, f3.x, f3.y);
            // pass 1: hi * Wlo
            mma16816(acc[0][n0 + 0], ah0, f0.z, f0.w);
            mma16816(acc[0][n0 + 1], ah0, f1.z, f1.w);
            mma16816(acc[0][n0 + 2], ah0, f2.z, f2.w);
            mma16816(acc[0][n0 + 3], ah0, f3.z, f3.w);
            mma16816(acc[1][n0 + 0], ah1, f0.z, f0.w);
            mma16816(acc[1][n0 + 1], ah1, f1.z, f1.w);
            mma16816(acc[1][n0 + 2], ah1, f2.z, f2.w);
            mma16816(acc[1][n0 + 3], ah1, f3.z, f3.w);
            // pass 2: lo * Whi
            mma16816(acc[0][n0 + 0], al0, f0.x, f0.y);
            mma16816(acc[0][n0 + 1], al0, f1.x, f1.y);
            mma16816(acc[0][n0 + 2], al0, f2.x, f2.y);
            mma16816(acc[0][n0 + 3], al0, f3.x, f3.y);
            mma16816(acc[1][n0 + 0], al1, f0.x, f0.y);
            mma16816(acc[1][n0 + 1], al1, f1.x, f1.y);
            mma16816(acc[1][n0 + 2], al1, f2.x, f2.y);
            mma16816(acc[1][n0 + 3], al1, f3.x, f3.y);
        }
    }

    // ---- epilogue ---------------------------------------------------------
    // Thread owns rows (per mt): r = 32*rw + 16*mt + g and r+8;
    // cols c = 64*ch + 8*nt + 2*t. x reconstructed from smem hi+lo
    // (exact to ~2^-19). Single-pass stats: S = sum(h), Q = sum(h^2);
    // var = Q/128 - mu^2 (no cancellation risk: h ~ N(0,~1.4), mu ~ 0.1).
    const int g = lane >> 2;
    const int t = lane & 3;
    const uint32_t cxor = (uint32_t)(4 * t);

    // Pass 1: h = x + V*flag, row sums + sums of squares
#pragma unroll
    for (int mt = 0; mt < 2; mt++) {
        const int r0 = 32 * rw + 16 * mt + g;
        const int r1 = r0 + 8;
        const int rc0 = min(row0 + r0, N_NODES - 1);
        const int rc1 = min(row0 + r1, N_NODES - 1);
        const float fac0 = (float)g_flag[rc0];
        const float fac1 = (float)g_flag[rc1];

        const uint32_t rbe0 = (uint32_t)(r0 >> 3) * 1024u + (uint32_t)(r0 & 7) * 128u
                            + ((uint32_t)ch << 13);
        const uint32_t rbe1 = (uint32_t)(r1 >> 3) * 1024u + (uint32_t)(r1 & 7) * 128u
                            + ((uint32_t)ch << 13);
        const uint32_t xe0 = (uint32_t)(r0 & 7) << 4;
        const uint32_t xe1 = (uint32_t)(r1 & 7) << 4;

        float s0 = 0.0f, s1 = 0.0f, q0 = 0.0f, q1 = 0.0f;
#pragma unroll
        for (int nt = 0; nt < 8; nt++) {
            const uint32_t cl = (uint32_t)(16 * nt) + cxor;     // (c&63)*2
            const uint32_t off0 = rbe0 + (cl ^ xe0);
            const uint32_t off1 = rbe1 + (cl ^ xe1);
            uint32_t xh0 = *(const uint32_t*)(smem + SM_XHI + off0);
            uint32_t xl0 = *(const uint32_t*)(smem + SM_XLO + off0);
            uint32_t xh1 = *(const uint32_t*)(smem + SM_XHI + off1);
            uint32_t xl1 = *(const uint32_t*)(smem + SM_XLO + off1);
            float2 x0 = bf2sum(xh0, xl0);
            float2 x1 = bf2sum(xh1, xl1);

            float h00 = fmaf(acc[mt][nt][0], fac0, x0.x);
            float h01 = fmaf(acc[mt][nt][1], fac0, x0.y);
            float h10 = fmaf(acc[mt][nt][2], fac1, x1.x);
            float h11 = fmaf(acc[mt][nt][3], fac1, x1.y);
            acc[mt][nt][0] = h00; acc[mt][nt][1] = h01;
            acc[mt][nt][2] = h10; acc[mt][nt][3] = h11;
            s0 += h00 + h01;
            s1 += h10 + h11;
            q0 = fmaf(h00, h00, fmaf(h01, h01, q0));
            q1 = fmaf(h10, h10, fmaf(h11, h11, q1));
        }
        s0 += __shfl_xor_sync(0xffffffffu, s0, 1);
        s0 += __shfl_xor_sync(0xffffffffu, s0, 2);
        s1 += __shfl_xor_sync(0xffffffffu, s1, 1);
        s1 += __shfl_xor_sync(0xffffffffu, s1, 2);
        q0 += __shfl_xor_sync(0xffffffffu, q0, 1);
        q0 += __shfl_xor_sync(0xffffffffu, q0, 2);
        q1 += __shfl_xor_sync(0xffffffffu, q1, 1);
        q1 += __shfl_xor_sync(0xffffffffu, q1, 2);
        if (t == 0) {
            psum[r0 * 2 + ch] = s0; psum[r1 * 2 + ch] = s1;
            psq[r0 * 2 + ch]  = q0; psq[r1 * 2 + ch]  = q1;
        }
    }
    __syncthreads();

    // re-zero flags for next graph replay (all facs of this CTA already read)
    if (tid < M_TILE) {
        int rz = row0 + tid;
        if (rz < N_NODES) g_flag[rz] = 0;
    }

    // Pass 2: normalize + store
#pragma unroll
    for (int mt = 0; mt < 2; mt++) {
        const int r0 = 32 * rw + 16 * mt + g;
        const int r1 = r0 + 8;
        const float mu0 = (psum[r0 * 2] + psum[r0 * 2 + 1]) * (1.0f / 128.0f);
        const float mu1 = (psum[r1 * 2] + psum[r1 * 2 + 1]) * (1.0f / 128.0f);
        const float var0 = fmaf(-mu0, mu0, (psq[r0 * 2] + psq[r0 * 2 + 1]) * (1.0f / 128.0f));
        const float var1 = fmaf(-mu1, mu1, (psq[r1 * 2] + psq[r1 * 2 + 1]) * (1.0f / 128.0f));
        const float inv0 = rsqrtf(var0 + 1e-5f);
        const float inv1 = rsqrtf(var1 + 1e-5f);

        const int row0g = row0 + r0;
        const int row1g = row0 + r1;

#pragma unroll
        for (int nt = 0; nt < 8; nt++) {
            const int c = 64 * ch + 8 * nt + 2 * t;
            float2 gm = *(const float2*)(sg + c);
            float2 bt = *(const float2*)(sb + c);
            if (row0g < N_NODES) {
                float2 o;
                o.x = fmaf((acc[mt][nt][0] - mu0) * inv0, gm.x, bt.x);
                o.y = fmaf((acc[mt][nt][1] - mu0) * inv0, gm.y, bt.y);
                *(float2*)(out + (size_t)row0g * 128 + c) = o;
            }
            if (row1g < N_NODES) {
                float2 o;
                o.x = fmaf((acc[mt][nt][2] - mu1) * inv1, gm.x, bt.x);
                o.y = fmaf((acc[mt][nt][3] - mu1) * inv1, gm.y, bt.y);
                *(float2*)(out + (size_t)row1g * 128 + c) = o;
            }
        }
    }
}

// ---------------------------------------------------------------------------
extern "C" void kernel_launch(void* const* d_in, const int* in_sizes, int n_in,
                              void* d_out, int out_size)
{
    const float* x          = (const float*)d_in[0];
    const int*   edge_index = (const int*)d_in[1];
    const float* Wv         = (const float*)d_in[5];
    const float* gamma      = (const float*)d_in[7];
    const float* beta       = (const float*)d_in[8];
    float*       out        = (float*)d_out;

    cudaFuncSetAttribute(fused_v_ln_kernel,
                         cudaFuncAttributeMaxDynamicSharedMemorySize, SM_DYN);

    prep_mark_kernel<<<WF_BLOCKS + MARK_BLOCKS, 256>>>(Wv, edge_index);
    fused_v_ln_kernel<<<N_BLOCKS, THREADS, SM_DYN>>>(x, gamma, beta, out);
}